// round 13
// baseline (speedup 1.0000x reference)
#include <cuda_runtime.h>
#include <math.h>

#define NB 8
#define AA 3
#define HH 200
#define WW 336
#define HWP (HH*WW)          // 67200
#define AHW (AA*HWP)         // 201600
#define AHW4 (AHW/4)         // 50400
#define PRE 2000
#define POST 1000
#define THR 0.7f
#define MAXOFF 4.135166556742356f
#define CAP 4096
#define NBINS 65536
#define STATIC_BIN 49164     // logit-key bin of ~2.1875 (score ~0.9)
#define LOWSCAN 49152        // logit-key bin of 2.0 -- hist/scan window start
#define MW 32
#define ROWS_PAD 2048
// scan geometry
#define BS 128               // rows per scan block
#define NBLK 16              // ceil(PRE/BS)
#define TSW 33               // tile row stride in words (pad)
#define SCAN_SMEM (3*BS*TSW*8)

__device__ unsigned int        g_hist[NB*NBINS];
__device__ int                 g_cnt[NB];
__device__ unsigned long long  g_cand[NB*CAP];
__device__ float4              g_boxes[NB*PRE];
__device__ float               g_sc[NB*PRE];
// row-major: g_mask[n][row][word], only words w >= row/64 are valid
__device__ unsigned long long  g_mask[(size_t)NB*ROWS_PAD*MW];

// orderable key of raw logit (monotone with sigmoid)
__device__ __forceinline__ unsigned lkey(float x){
    unsigned b = __float_as_uint(x);
    return (b & 0x80000000u) ? ~b : (b | 0x80000000u);
}

// exact reference score key (sigmoid), computed only for candidates
__device__ __forceinline__ unsigned skey(float x){
    float s = 1.0f/(1.0f + expf(-x));
    return __float_as_uint(s) | 0x80000000u;   // s > 0 -> orderable
}

__device__ __forceinline__ void emit_cand(int n, float x, int el){
    int pos = atomicAdd(&g_cnt[n], 1);
    if (pos < CAP){
        int a = el / HWP;
        int pix = el - a*HWP;
        unsigned idx = (unsigned)(pix*AA + a);     // score-space index
        g_cand[n*CAP + pos] =
            ((unsigned long long)skey(x) << 32) | (unsigned long long)(0xFFFFFFFFu - idx);
    }
}

// hist on logit bins (only bins >= LOWSCAN) + opportunistic gather (bin >= STATIC_BIN)
__global__ void k_hist(const float4* __restrict__ logits){
    int n = blockIdx.y;
    int t = blockIdx.x*blockDim.x + threadIdx.x;
    if (t >= AHW4) return;
    float4 v = logits[(size_t)n*AHW4 + t];
    float vv[4] = {v.x, v.y, v.z, v.w};
    #pragma unroll
    for (int k = 0; k < 4; k++){
        unsigned bin = lkey(vv[k]) >> 16;
        if (bin >= LOWSCAN){
            atomicAdd(&g_hist[n*NBINS + bin], 1u);
            if (bin >= STATIC_BIN) emit_cand(n, vv[k], t*4 + k);
        }
    }
}

__device__ __forceinline__ void ce_reg(unsigned long long &a, unsigned long long &b, bool desc){
    if (desc ? (a < b) : (a > b)){ unsigned long long t=a; a=b; b=t; }
}

// stages j = jmax..1 (jmax <= 64) on the 128-element block b, warp-local
__device__ __forceinline__ void reg_stages(unsigned long long r[4], int b, int lane,
                                           int ksz, int jmax){
    if (jmax >= 64){
        bool d0 = (((b*128 + 0*32 + lane) & ksz) == 0);
        bool d1 = (((b*128 + 1*32 + lane) & ksz) == 0);
        ce_reg(r[0], r[2], d0);
        ce_reg(r[1], r[3], d1);
    }
    if (jmax >= 32){
        bool d0 = (((b*128 + 0*32 + lane) & ksz) == 0);
        bool d2 = (((b*128 + 2*32 + lane) & ksz) == 0);
        ce_reg(r[0], r[1], d0);
        ce_reg(r[2], r[3], d2);
    }
    int js = (jmax < 16) ? jmax : 16;
    for (int j = js; j >= 1; j >>= 1){
        #pragma unroll
        for (int k = 0; k < 4; k++){
            unsigned long long partner = __shfl_xor_sync(0xFFFFFFFFu, r[k], j);
            int idx_low = b*128 + k*32 + (lane & ~j);
            bool desc = ((idx_low & ksz) == 0);
            bool lower = ((lane & j) == 0);
            bool take_max = (lower == desc);
            r[k] = take_max ? (r[k] > partner ? r[k] : partner)
                            : (r[k] < partner ? r[k] : partner);
        }
    }
}

// thresh + filter + (fallback gather) + adaptive bitonic sort + decode
__global__ __launch_bounds__(1024) void k_sortdecode(const float4* __restrict__ logits,
                             const float* __restrict__ regs,
                             const float* __restrict__ anchors,
                             const int*   __restrict__ sizes){
    int n = blockIdx.x;
    int tid = threadIdx.x;   // 1024 threads = 32 warps
    int lane = tid & 31;
    int b    = tid >> 5;     // warp id = 128-element block id
    __shared__ unsigned long long s[CAP];
    __shared__ unsigned wsuf[32];
    __shared__ unsigned sh_skth;
    __shared__ int tstar, sh_thr, sh_fast, sh_cnt, fcnt;

    // ---- threshold from histogram (windowed scan; rare full rebuild) ----
    for (int pass = 0; pass < 2; pass++){
        unsigned* seg = (unsigned*)s;
        int per = pass ? 64 : 16;              // bins per thread
        int base_bin = pass ? 0 : LOWSCAN;
        const uint4* hp = (const uint4*)(g_hist + n*NBINS + base_bin + tid*per);
        unsigned acc = 0;
        for (int k = 0; k < per/4; k++){ uint4 v = hp[k]; acc += v.x+v.y+v.z+v.w; }
        unsigned a = acc;
        #pragma unroll
        for (int off=1; off<32; off<<=1){
            unsigned v = __shfl_down_sync(0xFFFFFFFFu, a, off);
            if (lane < 32-off) a += v;
        }
        if (lane == 0) wsuf[b] = a;
        __syncthreads();
        if (tid < 32){
            unsigned w = wsuf[tid];
            #pragma unroll
            for (int off=1; off<32; off<<=1){
                unsigned v = __shfl_down_sync(0xFFFFFFFFu, w, off);
                if (tid < 32-off) w += v;
            }
            wsuf[tid] = w;
        }
        __syncthreads();
        unsigned total = wsuf[0];
        if (total >= PRE){
            unsigned suf = a + ((b < 31) ? wsuf[b+1] : 0u);
            seg[tid] = suf;
            __syncthreads();
            if (suf >= PRE && (tid==1023 || seg[tid+1] < PRE)) tstar = tid;
            __syncthreads();
            if (tid==0){
                int t = tstar;
                unsigned cum = (t < 1023) ? seg[t+1] : 0u;
                int T = base_bin + t*per;
                for (int bb = t*per + per - 1; bb >= t*per; bb--){
                    cum += g_hist[n*NBINS + base_bin + bb];
                    if (cum >= PRE){ T = base_bin + bb; break; }
                }
                int thrv = (T > 0) ? (T - 1) : 0;      // one-bin safety margin
                int cnt0 = atomicAdd(&g_cnt[n], 0);
                bool fast = (STATIC_BIN <= thrv) && (cnt0 <= CAP);
                sh_thr = thrv; sh_fast = fast ? 1 : 0; sh_cnt = cnt0;
                if (fast){
                    // skey of lower logit edge of exact cutoff bin T, minus 64 ULP slack
                    unsigned Tb = (unsigned)(thrv + 1);
                    float L0 = __uint_as_float((Tb << 16) ^ 0x80000000u);
                    unsigned sk = skey(L0);
                    sh_skth = (sk > 64u) ? (sk - 64u) : 0u;
                } else {
                    atomicExch(&g_cnt[n], 0);          // re-gather from scratch
                }
                fcnt = 0;
            }
            __syncthreads();
            break;
        }
        // pathological: rebuild the skipped low bins exactly, then full rescan
        for (int t = tid; t < AHW4; t += 1024){
            float4 v = logits[(size_t)n*AHW4 + t];
            float vv[4] = {v.x, v.y, v.z, v.w};
            #pragma unroll
            for (int k=0;k<4;k++){
                unsigned bin = lkey(vv[k]) >> 16;
                if (bin < LOWSCAN) atomicAdd(&g_hist[n*NBINS + bin], 1u);
            }
        }
        __syncthreads();
    }

    int f;  // number of live entries in s
    if (sh_fast){
        // filter candidates by exact score-key threshold (provable superset)
        unsigned skth = sh_skth;
        int cnt = sh_cnt;
        for (int k = tid; k < cnt; k += 1024){
            unsigned long long v = g_cand[n*CAP + k];
            if ((unsigned)(v >> 32) >= skth){
                int p = atomicAdd(&fcnt, 1);
                s[p] = v;
            }
        }
        __syncthreads();
        f = fcnt;
        if (f < PRE){           // paranoia: filter too tight -> use all
            __syncthreads();
            for (int k = tid; k < cnt; k += 1024) s[k] = g_cand[n*CAP + k];
            f = cnt;
        }
    } else {
        // fallback gather with the exact histogram threshold
        int thr = sh_thr;
        for (int t = tid; t < AHW4; t += 1024){
            float4 v = logits[(size_t)n*AHW4 + t];
            float vv[4] = {v.x, v.y, v.z, v.w};
            #pragma unroll
            for (int k=0;k<4;k++){
                if ((int)(lkey(vv[k]) >> 16) >= thr) emit_cand(n, vv[k], t*4 + k);
            }
        }
        __syncthreads();
        if (tid == 0) sh_cnt = atomicAdd(&g_cnt[n], 0);
        __syncthreads();
        f = sh_cnt; if (f > CAP) f = CAP;
        for (int k = tid; k < f; k += 1024) s[k] = g_cand[n*CAP + k];
    }
    int SORTN = (f <= 2048) ? 2048 : CAP;
    for (int k = tid; k < SORTN; k += 1024) if (k >= f) s[k] = 0ull;
    __syncthreads();

    // Phase A: all ksz=2..128 stages, warp-local (registers + shfl)
    if (b < SORTN/128){
        unsigned long long r[4];
        #pragma unroll
        for (int k = 0; k < 4; k++) r[k] = s[b*128 + k*32 + lane];
        #pragma unroll
        for (int ksz = 2; ksz <= 128; ksz <<= 1)
            reg_stages(r, b, lane, ksz, ksz >> 1);
        #pragma unroll
        for (int k = 0; k < 4; k++) s[b*128 + k*32 + lane] = r[k];
    }
    __syncthreads();

    // Phase B: ksz = 256..SORTN; paired smem stages for j>=128, reg phase j<=64
    for (int ksz = 256; ksz <= SORTN; ksz <<= 1){
        int j = ksz >> 1;
        while (j >= 256){
            if (tid < SORTN/4){
                int j1 = j, j2 = j >> 1;
                int s2 = __ffs(j2) - 1;
                int c = tid;
                int idx = ((c >> s2) << (s2+2)) | (c & (j2-1));
                unsigned long long e0 = s[idx];
                unsigned long long e1 = s[idx + j2];
                unsigned long long e2 = s[idx + j1];
                unsigned long long e3 = s[idx + j1 + j2];
                bool desc = ((idx & ksz) == 0);
                ce_reg(e0, e2, desc); ce_reg(e1, e3, desc);   // stage j1
                ce_reg(e0, e1, desc); ce_reg(e2, e3, desc);   // stage j2
                s[idx] = e0; s[idx + j2] = e1; s[idx + j1] = e2; s[idx + j1 + j2] = e3;
            }
            __syncthreads();
            j >>= 2;
        }
        if (j == 128){
            for (int c = tid; c < SORTN/2; c += 1024){
                int idx = ((c >> 7) << 8) | (c & 127);
                int p = idx | 128;
                unsigned long long a = s[idx], bb2 = s[p];
                bool desc = ((idx & ksz) == 0);
                if (desc ? (a < bb2) : (a > bb2)){ s[idx] = bb2; s[p] = a; }
            }
            __syncthreads();
        }
        if (b < SORTN/128){
            unsigned long long r[4];
            #pragma unroll
            for (int k = 0; k < 4; k++) r[k] = s[b*128 + k*32 + lane];
            reg_stages(r, b, lane, ksz, 64);
            #pragma unroll
            for (int k = 0; k < 4; k++) s[b*128 + k*32 + lane] = r[k];
        }
        __syncthreads();
    }

    float fh = (float)sizes[n*2+0];
    float fw = (float)sizes[n*2+1];
    for (int r = tid; r < PRE; r += 1024){
        unsigned long long v = s[r];
        unsigned key = (unsigned)(v >> 32);
        unsigned idx = 0xFFFFFFFFu - (unsigned)(v & 0xFFFFFFFFull);
        float score = __uint_as_float(key ^ 0x80000000u);
        float4 anc = ((const float4*)anchors)[(size_t)n*AHW + idx];
        int a = (int)(idx % (unsigned)AA);
        int pix = (int)(idx / (unsigned)AA);
        const float* rb = regs + (size_t)n*(AA*4*HWP) + (size_t)a*4*HWP + pix;
        float r0 = rb[0];
        float r1 = rb[HWP];
        float r2 = rb[2*HWP];
        float r3 = rb[3*HWP];
        float ws = anc.z - anc.x + 1.0f;
        float hs = anc.w - anc.y + 1.0f;
        float xc = anc.x + 0.5f*ws;
        float yc = anc.y + 0.5f*hs;
        float dw = fminf(r2, MAXOFF);
        float dh = fminf(r3, MAXOFF);
        xc = xc + r0*ws;
        yc = yc + r1*hs;
        ws = ws * expf(dw);
        hs = hs * expf(dh);
        float x1 = xc - 0.5f*ws;
        float y1 = yc - 0.5f*hs;
        float x2 = xc + 0.5f*ws - 1.0f;
        float y2 = yc + 0.5f*hs - 1.0f;
        x1 = fminf(fmaxf(x1, 0.0f), fw - 1.0f);
        y1 = fminf(fmaxf(y1, 0.0f), fh - 1.0f);
        x2 = fminf(fmaxf(x2, 0.0f), fw - 1.0f);
        y2 = fminf(fmaxf(y2, 0.0f), fh - 1.0f);
        g_boxes[n*PRE + r] = make_float4(x1,y1,x2,y2);
        g_sc[n*PRE + r] = score;
    }
}

// Upper-triangle tile IoU mask. grid = (528, NB), 256 threads.
// Tail: re-zero g_hist for the next call.
__global__ void k_mask(){
    int n = blockIdx.y;
    int p = blockIdx.x;
    int ti = 0;
    while (p >= 32 - ti){ p -= 32 - ti; ti++; }
    int tj = ti + p;

    __shared__ float4 rb[64];
    __shared__ float4 cb[64];
    __shared__ float  ca[64];
    int tid = threadIdx.x;
    if (tid < 64){
        int gi = ti*64 + tid;
        rb[tid] = (gi < PRE) ? g_boxes[n*PRE + gi] : make_float4(0.f,0.f,-1.f,-1.f);
    } else if (tid < 128){
        int t = tid - 64;
        int gj = tj*64 + t;
        float4 b = (gj < PRE) ? g_boxes[n*PRE + gj] : make_float4(0.f,0.f,-1.f,-1.f);
        cb[t] = b;
        ca[t] = (b.z - b.x + 1.0f) * (b.w - b.y + 1.0f);
    }
    __syncthreads();

    int rid = tid >> 3;       // 0..31
    int q   = tid & 7;
    int iA = ti*64 + rid;
    int iB = iA + 32;
    float4 bA = rb[rid];
    float4 bB = rb[rid + 32];
    float aA = (bA.z - bA.x + 1.0f) * (bA.w - bA.y + 1.0f);
    float aB = (bB.z - bB.x + 1.0f) * (bB.w - bB.y + 1.0f);

    unsigned long long wA = 0ull, wB = 0ull;
    #pragma unroll
    for (int jj = 0; jj < 8; jj++){
        int j = jj*8 + q;            // strided -> conflict-free LDS across q
        int jg = tj*64 + j;
        if (jg >= PRE) continue;
        float4 bj = cb[j];
        float aj = ca[j];
        float xtlA = fmaxf(bA.x, bj.x), ytlA = fmaxf(bA.y, bj.y);
        float xbrA = fminf(bA.z, bj.z), ybrA = fminf(bA.w, bj.w);
        float iwA = fmaxf(xbrA - xtlA + 1.0f, 0.0f);
        float ihA = fmaxf(ybrA - ytlA + 1.0f, 0.0f);
        float interA = iwA * ihA;
        float denomA = aA + aj - interA;
        if (jg > iA && interA > 0.6f * denomA)
            if (interA / denomA > THR) wA |= (1ull << j);
        float xtlB = fmaxf(bB.x, bj.x), ytlB = fmaxf(bB.y, bj.y);
        float xbrB = fminf(bB.z, bj.z), ybrB = fminf(bB.w, bj.w);
        float iwB = fmaxf(xbrB - xtlB + 1.0f, 0.0f);
        float ihB = fmaxf(ybrB - ytlB + 1.0f, 0.0f);
        float interB = iwB * ihB;
        float denomB = aB + aj - interB;
        if (jg > iB && interB > 0.6f * denomB)
            if (interB / denomB > THR) wB |= (1ull << j);
    }
    wA |= __shfl_xor_sync(0xFFFFFFFFu, wA, 1, 8);
    wA |= __shfl_xor_sync(0xFFFFFFFFu, wA, 2, 8);
    wA |= __shfl_xor_sync(0xFFFFFFFFu, wA, 4, 8);
    wB |= __shfl_xor_sync(0xFFFFFFFFu, wB, 1, 8);
    wB |= __shfl_xor_sync(0xFFFFFFFFu, wB, 2, 8);
    wB |= __shfl_xor_sync(0xFFFFFFFFu, wB, 4, 8);
    if (q == 0){
        if (iA < PRE) g_mask[((size_t)n*ROWS_PAD + iA)*MW + tj] = wA;
        if (iB < PRE) g_mask[((size_t)n*ROWS_PAD + iB)*MW + tj] = wB;
    }

    // tail: zero g_hist for the next call (independent of this kernel's data)
    unsigned gid = (blockIdx.y*gridDim.x + blockIdx.x)*blockDim.x + threadIdx.x;
    if (gid < (unsigned)(NB*NBINS/4))
        ((uint4*)g_hist)[gid] = make_uint4(0,0,0,0);
}

// Warp-specialized pipelined NMS scan, 128-row blocks (16 iterations).
// Warp 0: two-word chain + quick-OR onto the next block's two words.
// Warps 1-15: tile staging (2-deep register prefetch) + bulk OR of block B-1
// onto words >= 2B+2. All remv contributions via atomicOr. 1 barrier/iter.
__global__ __launch_bounds__(512) void k_scan(float* __restrict__ out){
    extern __shared__ unsigned long long tile[];   // [3][BS*TSW]
    int n = blockIdx.x;
    int tid = threadIdx.x;    // 512 = 16 warps
    int lane = tid & 31;
    int wrp  = tid >> 5;
    __shared__ unsigned long long remv[MW];
    __shared__ unsigned long long sh_alive[2][2];
    __shared__ int sh_stop;
    __shared__ int kb[MW+1];
    if (tid < MW) remv[tid] = 0ull;
    if (tid == 0) sh_stop = NBLK;

    const unsigned long long* gb = &g_mask[((size_t)n*ROWS_PAD)*MW];
    // stage tile 0 (all threads): 128 rows x 32 words (rows 0..127 < PRE)
    #pragma unroll
    for (int q = 0; q < 8; q++){
        int k = tid + q*512;
        tile[(size_t)(k >> 5)*TSW + (k & 31)] = gb[k];
    }
    // prefetch tile 1 (workers; rows 128..255 < PRE)
    unsigned long long pf[9];
    int ptid = tid - 32;      // 0..479
    if (wrp > 0){
        #pragma unroll
        for (int q = 0; q < 9; q++){
            int k = ptid + q*480;
            if (k < BS*MW) pf[q] = gb[BS*MW + k];
        }
    }
    __syncthreads();

    int kept_total = 0;       // warp0 lane0 only
    for (int B = 0; B < NBLK; B++){
        int cur = B % 3, stb = (B+1) % 3, prv = (B+2) % 3;
        int base = B*BS;
        int nrows = PRE - base; if (nrows > BS) nrows = BS;
        unsigned long long* tcur = tile + (size_t)cur*BS*TSW;

        if (wrp == 0){
            if (lane == 0){
                unsigned long long w0 = remv[2*B];
                unsigned long long w1 = remv[2*B+1];
                int c0 = 2*B, c1 = 2*B+1;
                unsigned long long A0[8], A1[8], Bb0[8], Bb1[8];
                #pragma unroll
                for (int k = 0; k < 8; k++){
                    A0[k] = tcur[k*TSW + c0];
                    A1[k] = tcur[k*TSW + c1];
                }
                #pragma unroll
                for (int c = 0; c < 16; c++){
                    if (c < 15){
                        #pragma unroll
                        for (int k = 0; k < 8; k++){
                            int r = (c+1)*8 + k;
                            if (c & 1){ A0[k] = tcur[r*TSW + c0]; A1[k] = tcur[r*TSW + c1]; }
                            else      { Bb0[k] = tcur[r*TSW + c0]; Bb1[k] = tcur[r*TSW + c1]; }
                        }
                    }
                    #pragma unroll
                    for (int k = 0; k < 8; k++){
                        int rr = c*8 + k;
                        unsigned long long m0 = (c & 1) ? Bb0[k] : A0[k];
                        unsigned long long m1 = (c & 1) ? Bb1[k] : A1[k];
                        unsigned long long bit = (rr < 64) ? (w0 >> rr) : (w1 >> (rr - 64));
                        unsigned long long msk = (bit & 1ull) - 1ull;   // ~0 if alive
                        w0 |= m0 & msk;
                        w1 |= m1 & msk;
                    }
                }
                remv[2*B]   = w0;
                remv[2*B+1] = w1;
                unsigned long long v0 = (nrows >= 64) ? ~0ull : ((1ull << nrows) - 1ull);
                unsigned long long v1 = (nrows >= 128) ? ~0ull
                                       : (nrows > 64 ? ((1ull << (nrows-64)) - 1ull) : 0ull);
                unsigned long long a0 = (~w0) & v0;
                unsigned long long a1 = (~w1) & v1;
                sh_alive[B & 1][0] = a0;
                sh_alive[B & 1][1] = a1;
                kept_total += __popcll(a0) + __popcll(a1);
                if (kept_total >= POST && B + 1 < NBLK) sh_stop = B + 1;
            }
            __syncwarp();
            // quick OR: block B's alive rows onto words 2B+2, 2B+3
            if (B + 1 < NBLK){
                unsigned long long a0 = sh_alive[B & 1][0];
                unsigned long long a1 = sh_alive[B & 1][1];
                #pragma unroll
                for (int cc = 0; cc < 2; cc++){
                    int cw = 2*B + 2 + cc;
                    unsigned long long acc = 0ull;
                    if ((a0 >> lane) & 1ull)        acc  = tcur[lane*TSW + cw];
                    if ((a0 >> (lane+32)) & 1ull)   acc |= tcur[(lane+32)*TSW + cw];
                    if ((a1 >> lane) & 1ull)        acc |= tcur[(lane+64)*TSW + cw];
                    if ((a1 >> (lane+32)) & 1ull)   acc |= tcur[(lane+96)*TSW + cw];
                    unsigned lo = __reduce_or_sync(0xFFFFFFFFu, (unsigned)acc);
                    unsigned hi = __reduce_or_sync(0xFFFFFFFFu, (unsigned)(acc >> 32));
                    if (lane == 0){
                        unsigned long long a = ((unsigned long long)hi << 32) | (unsigned long long)lo;
                        if (a) atomicOr(&remv[cw], a);
                    }
                }
            }
        } else {
            // store prefetched tile B+1
            if (B + 1 < NBLK){
                unsigned long long* tst = tile + (size_t)stb*BS*TSW;
                #pragma unroll
                for (int q = 0; q < 9; q++){
                    int k = ptid + q*480;
                    if (k < BS*MW) tst[(size_t)(k >> 5)*TSW + (k & 31)] = pf[q];
                }
            }
            // issue prefetch for tile B+2 (zero rows >= PRE)
            if (B + 2 < NBLK){
                const unsigned long long* gp = gb + (size_t)(B+2)*BS*MW;
                int grow0 = (B+2)*BS;
                #pragma unroll
                for (int q = 0; q < 9; q++){
                    int k = ptid + q*480;
                    if (k < BS*MW){
                        int grow = grow0 + (k >> 5);
                        pf[q] = (grow < PRE) ? gp[k] : 0ull;
                    }
                }
            }
            // bulk OR: block B-1's alive rows onto words >= 2B+2
            if (B >= 1 && lane >= 2*B + 2){
                unsigned long long a0 = sh_alive[(B-1) & 1][0];
                unsigned long long a1 = sh_alive[(B-1) & 1][1];
                const unsigned long long* tp = tile + (size_t)prv*BS*TSW;
                unsigned long long acc = 0ull;
                for (int rr = wrp - 1; rr < BS; rr += 15){
                    unsigned long long bit = (rr < 64) ? (a0 >> rr) : (a1 >> (rr - 64));
                    if (bit & 1ull) acc |= tp[(size_t)rr*TSW + lane];
                }
                if (acc) atomicOr(&remv[lane], acc);
            }
        }
        __syncthreads();
        if (B + 1 >= sh_stop) break;       // kept >= POST: rest irrelevant
    }

    if (tid == 0){
        int c = 0;
        for (int ww = 0; ww < MW; ww++){
            kb[ww] = c;
            unsigned long long valid = (ww == MW-1) ? 0xFFFFull : ~0ull;
            c += __popcll((~remv[ww]) & valid);
        }
        kb[MW] = c;
        g_cnt[n] = 0;           // tail: reset candidate counter for next call
    }
    __syncthreads();
    // stable partition: kept (in order) then suppressed (in order) == post top_k
    for (int i = tid; i < PRE; i += 512){
        int ww = i >> 6, b = i & 63;
        unsigned long long valid = (ww == MW-1) ? 0xFFFFull : ~0ull;
        unsigned long long notr = (~remv[ww]) & valid;
        bool keep = (notr >> b) & 1ull;
        unsigned long long below = b ? (notr & ((~0ull) >> (64 - b))) : 0ull;
        int kbelow = kb[ww] + __popcll(below);
        int pos = keep ? kbelow : (kb[MW] + (i - kbelow));
        if (pos < POST){
            float4 bx = g_boxes[n*PRE + i];
            float sc = keep ? g_sc[n*PRE + i] : -1.0f;
            float* op = out + ((size_t)n*POST + pos)*5;
            op[0]=bx.x; op[1]=bx.y; op[2]=bx.z; op[3]=bx.w; op[4]=sc;
        }
    }
}

extern "C" void kernel_launch(void* const* d_in, const int* in_sizes, int n_in,
                              void* d_out, int out_size){
    (void)in_sizes; (void)n_in; (void)out_size;
    const float* logits  = (const float*)d_in[0];
    const float* regs    = (const float*)d_in[1];
    const float* anchors = (const float*)d_in[2];
    const int*   sizes   = (const int*)d_in[3];
    float* out = (float*)d_out;

    cudaFuncSetAttribute(k_scan, cudaFuncAttributeMaxDynamicSharedMemorySize, SCAN_SMEM);

    dim3 g((AHW4 + 255)/256, NB);
    k_hist<<<g, 256>>>((const float4*)logits);
    k_sortdecode<<<NB, 1024>>>((const float4*)logits, regs, anchors, sizes);
    k_mask<<<dim3(528, NB), 256>>>();
    k_scan<<<NB, 512, SCAN_SMEM>>>(out);
}

// round 14
// speedup vs baseline: 1.1192x; 1.1192x over previous
#include <cuda_runtime.h>
#include <math.h>

#define NB 8
#define AA 3
#define HH 200
#define WW 336
#define HWP (HH*WW)          // 67200
#define AHW (AA*HWP)         // 201600
#define AHW4 (AHW/4)         // 50400
#define PRE 2000
#define POST 1000
#define THR 0.7f
#define MAXOFF 4.135166556742356f
#define CAP 4096
#define NBINS 65536
#define STATIC_BIN 49164     // logit-key bin of ~2.1875 (score ~0.9)
#define LOWSCAN 49152        // logit-key bin of 2.0 -- hist/scan window start
#define MW 32
#define ROWS_PAD 2048

__device__ unsigned int        g_hist[NB*NBINS];
__device__ int                 g_cnt[NB];
__device__ unsigned long long  g_cand[NB*CAP];
__device__ float4              g_boxes[NB*PRE];
__device__ float               g_sc[NB*PRE];
// row-major: g_mask[n][row][word], only words w >= row/64 are valid
__device__ unsigned long long  g_mask[(size_t)NB*ROWS_PAD*MW];

// orderable key of raw logit (monotone with sigmoid)
__device__ __forceinline__ unsigned lkey(float x){
    unsigned b = __float_as_uint(x);
    return (b & 0x80000000u) ? ~b : (b | 0x80000000u);
}

// exact reference score key (sigmoid), computed only for candidates
__device__ __forceinline__ unsigned skey(float x){
    float s = 1.0f/(1.0f + expf(-x));
    return __float_as_uint(s) | 0x80000000u;   // s > 0 -> orderable
}

__device__ __forceinline__ void emit_cand(int n, float x, int el){
    int pos = atomicAdd(&g_cnt[n], 1);
    if (pos < CAP){
        int a = el / HWP;
        int pix = el - a*HWP;
        unsigned idx = (unsigned)(pix*AA + a);     // score-space index
        g_cand[n*CAP + pos] =
            ((unsigned long long)skey(x) << 32) | (unsigned long long)(0xFFFFFFFFu - idx);
    }
}

// hist on logit bins (only bins >= LOWSCAN) + opportunistic gather (bin >= STATIC_BIN)
__global__ void k_hist(const float4* __restrict__ logits){
    int n = blockIdx.y;
    int t = blockIdx.x*blockDim.x + threadIdx.x;
    if (t >= AHW4) return;
    float4 v = logits[(size_t)n*AHW4 + t];
    float vv[4] = {v.x, v.y, v.z, v.w};
    #pragma unroll
    for (int k = 0; k < 4; k++){
        unsigned bin = lkey(vv[k]) >> 16;
        if (bin >= LOWSCAN){
            atomicAdd(&g_hist[n*NBINS + bin], 1u);
            if (bin >= STATIC_BIN) emit_cand(n, vv[k], t*4 + k);
        }
    }
}

__device__ __forceinline__ void ce_reg(unsigned long long &a, unsigned long long &b, bool desc){
    if (desc ? (a < b) : (a > b)){ unsigned long long t=a; a=b; b=t; }
}

// stages j = jmax..1 (jmax <= 64) on the 128-element block b, warp-local
__device__ __forceinline__ void reg_stages(unsigned long long r[4], int b, int lane,
                                           int ksz, int jmax){
    if (jmax >= 64){
        bool d0 = (((b*128 + 0*32 + lane) & ksz) == 0);
        bool d1 = (((b*128 + 1*32 + lane) & ksz) == 0);
        ce_reg(r[0], r[2], d0);
        ce_reg(r[1], r[3], d1);
    }
    if (jmax >= 32){
        bool d0 = (((b*128 + 0*32 + lane) & ksz) == 0);
        bool d2 = (((b*128 + 2*32 + lane) & ksz) == 0);
        ce_reg(r[0], r[1], d0);
        ce_reg(r[2], r[3], d2);
    }
    int js = (jmax < 16) ? jmax : 16;
    for (int j = js; j >= 1; j >>= 1){
        #pragma unroll
        for (int k = 0; k < 4; k++){
            unsigned long long partner = __shfl_xor_sync(0xFFFFFFFFu, r[k], j);
            int idx_low = b*128 + k*32 + (lane & ~j);
            bool desc = ((idx_low & ksz) == 0);
            bool lower = ((lane & j) == 0);
            bool take_max = (lower == desc);
            r[k] = take_max ? (r[k] > partner ? r[k] : partner)
                            : (r[k] < partner ? r[k] : partner);
        }
    }
}

// thresh + filter + (fallback gather) + adaptive bitonic sort + decode
__global__ __launch_bounds__(1024) void k_sortdecode(const float4* __restrict__ logits,
                             const float* __restrict__ regs,
                             const float* __restrict__ anchors,
                             const int*   __restrict__ sizes){
    int n = blockIdx.x;
    int tid = threadIdx.x;   // 1024 threads = 32 warps
    int lane = tid & 31;
    int b    = tid >> 5;     // warp id = 128-element block id
    __shared__ unsigned long long s[CAP];
    __shared__ unsigned wsuf[32];
    __shared__ unsigned sh_skth;
    __shared__ int tstar, sh_thr, sh_fast, sh_cnt, fcnt;

    // ---- threshold from histogram (windowed scan; rare full rebuild) ----
    for (int pass = 0; pass < 2; pass++){
        unsigned* seg = (unsigned*)s;
        int per = pass ? 64 : 16;              // bins per thread
        int base_bin = pass ? 0 : LOWSCAN;
        const uint4* hp = (const uint4*)(g_hist + n*NBINS + base_bin + tid*per);
        unsigned acc = 0;
        for (int k = 0; k < per/4; k++){ uint4 v = hp[k]; acc += v.x+v.y+v.z+v.w; }
        unsigned a = acc;
        #pragma unroll
        for (int off=1; off<32; off<<=1){
            unsigned v = __shfl_down_sync(0xFFFFFFFFu, a, off);
            if (lane < 32-off) a += v;
        }
        if (lane == 0) wsuf[b] = a;
        __syncthreads();
        if (tid < 32){
            unsigned w = wsuf[tid];
            #pragma unroll
            for (int off=1; off<32; off<<=1){
                unsigned v = __shfl_down_sync(0xFFFFFFFFu, w, off);
                if (tid < 32-off) w += v;
            }
            wsuf[tid] = w;
        }
        __syncthreads();
        unsigned total = wsuf[0];
        if (total >= PRE){
            unsigned suf = a + ((b < 31) ? wsuf[b+1] : 0u);
            seg[tid] = suf;
            __syncthreads();
            if (suf >= PRE && (tid==1023 || seg[tid+1] < PRE)) tstar = tid;
            __syncthreads();
            if (tid==0){
                int t = tstar;
                unsigned cum = (t < 1023) ? seg[t+1] : 0u;
                int T = base_bin + t*per;
                for (int bb = t*per + per - 1; bb >= t*per; bb--){
                    cum += g_hist[n*NBINS + base_bin + bb];
                    if (cum >= PRE){ T = base_bin + bb; break; }
                }
                int thrv = (T > 0) ? (T - 1) : 0;      // one-bin safety margin
                int cnt0 = atomicAdd(&g_cnt[n], 0);
                bool fast = (STATIC_BIN <= thrv) && (cnt0 <= CAP);
                sh_thr = thrv; sh_fast = fast ? 1 : 0; sh_cnt = cnt0;
                if (fast){
                    // skey of lower logit edge of exact cutoff bin T, minus 64 ULP slack
                    unsigned Tb = (unsigned)(thrv + 1);
                    float L0 = __uint_as_float((Tb << 16) ^ 0x80000000u);
                    unsigned sk = skey(L0);
                    sh_skth = (sk > 64u) ? (sk - 64u) : 0u;
                } else {
                    atomicExch(&g_cnt[n], 0);          // re-gather from scratch
                }
                fcnt = 0;
            }
            __syncthreads();
            break;
        }
        // pathological: rebuild the skipped low bins exactly, then full rescan
        for (int t = tid; t < AHW4; t += 1024){
            float4 v = logits[(size_t)n*AHW4 + t];
            float vv[4] = {v.x, v.y, v.z, v.w};
            #pragma unroll
            for (int k=0;k<4;k++){
                unsigned bin = lkey(vv[k]) >> 16;
                if (bin < LOWSCAN) atomicAdd(&g_hist[n*NBINS + bin], 1u);
            }
        }
        __syncthreads();
    }

    int f;  // number of live entries in s
    if (sh_fast){
        // filter candidates by exact score-key threshold (provable superset)
        unsigned skth = sh_skth;
        int cnt = sh_cnt;
        for (int k = tid; k < cnt; k += 1024){
            unsigned long long v = g_cand[n*CAP + k];
            if ((unsigned)(v >> 32) >= skth){
                int p = atomicAdd(&fcnt, 1);
                s[p] = v;
            }
        }
        __syncthreads();
        f = fcnt;
        if (f < PRE){           // paranoia: filter too tight -> use all
            __syncthreads();
            for (int k = tid; k < cnt; k += 1024) s[k] = g_cand[n*CAP + k];
            f = cnt;
        }
    } else {
        // fallback gather with the exact histogram threshold
        int thr = sh_thr;
        for (int t = tid; t < AHW4; t += 1024){
            float4 v = logits[(size_t)n*AHW4 + t];
            float vv[4] = {v.x, v.y, v.z, v.w};
            #pragma unroll
            for (int k=0;k<4;k++){
                if ((int)(lkey(vv[k]) >> 16) >= thr) emit_cand(n, vv[k], t*4 + k);
            }
        }
        __syncthreads();
        if (tid == 0) sh_cnt = atomicAdd(&g_cnt[n], 0);
        __syncthreads();
        f = sh_cnt; if (f > CAP) f = CAP;
        for (int k = tid; k < f; k += 1024) s[k] = g_cand[n*CAP + k];
    }
    int SORTN = (f <= 2048) ? 2048 : CAP;
    for (int k = tid; k < SORTN; k += 1024) if (k >= f) s[k] = 0ull;
    __syncthreads();

    // Phase A: all ksz=2..128 stages, warp-local (registers + shfl)
    if (b < SORTN/128){
        unsigned long long r[4];
        #pragma unroll
        for (int k = 0; k < 4; k++) r[k] = s[b*128 + k*32 + lane];
        #pragma unroll
        for (int ksz = 2; ksz <= 128; ksz <<= 1)
            reg_stages(r, b, lane, ksz, ksz >> 1);
        #pragma unroll
        for (int k = 0; k < 4; k++) s[b*128 + k*32 + lane] = r[k];
    }
    __syncthreads();

    // Phase B: ksz = 256..SORTN; paired smem stages for j>=128, reg phase j<=64
    for (int ksz = 256; ksz <= SORTN; ksz <<= 1){
        int j = ksz >> 1;
        while (j >= 256){
            if (tid < SORTN/4){
                int j1 = j, j2 = j >> 1;
                int s2 = __ffs(j2) - 1;
                int c = tid;
                int idx = ((c >> s2) << (s2+2)) | (c & (j2-1));
                unsigned long long e0 = s[idx];
                unsigned long long e1 = s[idx + j2];
                unsigned long long e2 = s[idx + j1];
                unsigned long long e3 = s[idx + j1 + j2];
                bool desc = ((idx & ksz) == 0);
                ce_reg(e0, e2, desc); ce_reg(e1, e3, desc);   // stage j1
                ce_reg(e0, e1, desc); ce_reg(e2, e3, desc);   // stage j2
                s[idx] = e0; s[idx + j2] = e1; s[idx + j1] = e2; s[idx + j1 + j2] = e3;
            }
            __syncthreads();
            j >>= 2;
        }
        if (j == 128){
            for (int c = tid; c < SORTN/2; c += 1024){
                int idx = ((c >> 7) << 8) | (c & 127);
                int p = idx | 128;
                unsigned long long a = s[idx], bb2 = s[p];
                bool desc = ((idx & ksz) == 0);
                if (desc ? (a < bb2) : (a > bb2)){ s[idx] = bb2; s[p] = a; }
            }
            __syncthreads();
        }
        if (b < SORTN/128){
            unsigned long long r[4];
            #pragma unroll
            for (int k = 0; k < 4; k++) r[k] = s[b*128 + k*32 + lane];
            reg_stages(r, b, lane, ksz, 64);
            #pragma unroll
            for (int k = 0; k < 4; k++) s[b*128 + k*32 + lane] = r[k];
        }
        __syncthreads();
    }

    float fh = (float)sizes[n*2+0];
    float fw = (float)sizes[n*2+1];
    for (int r = tid; r < PRE; r += 1024){
        unsigned long long v = s[r];
        unsigned key = (unsigned)(v >> 32);
        unsigned idx = 0xFFFFFFFFu - (unsigned)(v & 0xFFFFFFFFull);
        float score = __uint_as_float(key ^ 0x80000000u);
        float4 anc = ((const float4*)anchors)[(size_t)n*AHW + idx];
        int a = (int)(idx % (unsigned)AA);
        int pix = (int)(idx / (unsigned)AA);
        const float* rb = regs + (size_t)n*(AA*4*HWP) + (size_t)a*4*HWP + pix;
        float r0 = rb[0];
        float r1 = rb[HWP];
        float r2 = rb[2*HWP];
        float r3 = rb[3*HWP];
        float ws = anc.z - anc.x + 1.0f;
        float hs = anc.w - anc.y + 1.0f;
        float xc = anc.x + 0.5f*ws;
        float yc = anc.y + 0.5f*hs;
        float dw = fminf(r2, MAXOFF);
        float dh = fminf(r3, MAXOFF);
        xc = xc + r0*ws;
        yc = yc + r1*hs;
        ws = ws * expf(dw);
        hs = hs * expf(dh);
        float x1 = xc - 0.5f*ws;
        float y1 = yc - 0.5f*hs;
        float x2 = xc + 0.5f*ws - 1.0f;
        float y2 = yc + 0.5f*hs - 1.0f;
        x1 = fminf(fmaxf(x1, 0.0f), fw - 1.0f);
        y1 = fminf(fmaxf(y1, 0.0f), fh - 1.0f);
        x2 = fminf(fmaxf(x2, 0.0f), fw - 1.0f);
        y2 = fminf(fmaxf(y2, 0.0f), fh - 1.0f);
        g_boxes[n*PRE + r] = make_float4(x1,y1,x2,y2);
        g_sc[n*PRE + r] = score;
    }
}

// Upper-triangle tile IoU mask. grid = (528, NB), 256 threads.
// Tail: re-zero g_hist for the next call.
__global__ void k_mask(){
    int n = blockIdx.y;
    int p = blockIdx.x;
    int ti = 0;
    while (p >= 32 - ti){ p -= 32 - ti; ti++; }
    int tj = ti + p;

    __shared__ float4 rb[64];
    __shared__ float4 cb[64];
    __shared__ float  ca[64];
    int tid = threadIdx.x;
    if (tid < 64){
        int gi = ti*64 + tid;
        rb[tid] = (gi < PRE) ? g_boxes[n*PRE + gi] : make_float4(0.f,0.f,-1.f,-1.f);
    } else if (tid < 128){
        int t = tid - 64;
        int gj = tj*64 + t;
        float4 b = (gj < PRE) ? g_boxes[n*PRE + gj] : make_float4(0.f,0.f,-1.f,-1.f);
        cb[t] = b;
        ca[t] = (b.z - b.x + 1.0f) * (b.w - b.y + 1.0f);
    }
    __syncthreads();

    int rid = tid >> 3;       // 0..31
    int q   = tid & 7;
    int iA = ti*64 + rid;
    int iB = iA + 32;
    float4 bA = rb[rid];
    float4 bB = rb[rid + 32];
    float aA = (bA.z - bA.x + 1.0f) * (bA.w - bA.y + 1.0f);
    float aB = (bB.z - bB.x + 1.0f) * (bB.w - bB.y + 1.0f);

    unsigned long long wA = 0ull, wB = 0ull;
    #pragma unroll
    for (int jj = 0; jj < 8; jj++){
        int j = jj*8 + q;            // strided -> conflict-free LDS across q
        int jg = tj*64 + j;
        if (jg >= PRE) continue;
        float4 bj = cb[j];
        float aj = ca[j];
        float xtlA = fmaxf(bA.x, bj.x), ytlA = fmaxf(bA.y, bj.y);
        float xbrA = fminf(bA.z, bj.z), ybrA = fminf(bA.w, bj.w);
        float iwA = fmaxf(xbrA - xtlA + 1.0f, 0.0f);
        float ihA = fmaxf(ybrA - ytlA + 1.0f, 0.0f);
        float interA = iwA * ihA;
        float denomA = aA + aj - interA;
        if (jg > iA && interA > 0.6f * denomA)
            if (interA / denomA > THR) wA |= (1ull << j);
        float xtlB = fmaxf(bB.x, bj.x), ytlB = fmaxf(bB.y, bj.y);
        float xbrB = fminf(bB.z, bj.z), ybrB = fminf(bB.w, bj.w);
        float iwB = fmaxf(xbrB - xtlB + 1.0f, 0.0f);
        float ihB = fmaxf(ybrB - ytlB + 1.0f, 0.0f);
        float interB = iwB * ihB;
        float denomB = aB + aj - interB;
        if (jg > iB && interB > 0.6f * denomB)
            if (interB / denomB > THR) wB |= (1ull << j);
    }
    wA |= __shfl_xor_sync(0xFFFFFFFFu, wA, 1, 8);
    wA |= __shfl_xor_sync(0xFFFFFFFFu, wA, 2, 8);
    wA |= __shfl_xor_sync(0xFFFFFFFFu, wA, 4, 8);
    wB |= __shfl_xor_sync(0xFFFFFFFFu, wB, 1, 8);
    wB |= __shfl_xor_sync(0xFFFFFFFFu, wB, 2, 8);
    wB |= __shfl_xor_sync(0xFFFFFFFFu, wB, 4, 8);
    if (q == 0){
        if (iA < PRE) g_mask[((size_t)n*ROWS_PAD + iA)*MW + tj] = wA;
        if (iB < PRE) g_mask[((size_t)n*ROWS_PAD + iB)*MW + tj] = wB;
    }

    // tail: zero g_hist for the next call (independent of this kernel's data)
    unsigned gid = (blockIdx.y*gridDim.x + blockIdx.x)*blockDim.x + threadIdx.x;
    if (gid < (unsigned)(NB*NBINS/4))
        ((uint4*)g_hist)[gid] = make_uint4(0,0,0,0);
}

// Warp-specialized pipelined NMS scan (proven R10 structure): warp 0 = chain
// (with zero-chunk skip) + quick-OR (REDUX); warps 1-15 = bulk OR of previous
// block + tile staging with 2-deep register prefetch. 1 barrier/iter.
#define TS 33
__global__ __launch_bounds__(512) void k_scan(float* __restrict__ out){
    int n = blockIdx.x;
    int tid = threadIdx.x;    // 512 = 16 warps
    int lane = tid & 31;
    int wrp  = tid >> 5;
    __shared__ unsigned long long remv[MW];
    __shared__ unsigned long long tile[3][64*TS];
    __shared__ unsigned long long sh_alive[2];
    __shared__ int sh_stop;
    __shared__ int kb[MW+1];
    if (tid < MW) remv[tid] = 0ull;
    if (tid == 0) sh_stop = MW;

    const unsigned long long* gbase = &g_mask[((size_t)n*ROWS_PAD)*MW];
    // stage tile 0 (all threads)
    #pragma unroll
    for (int q = 0; q < 4; q++){
        int k = tid + q*512;
        tile[0][(k >> 5)*TS + (k & 31)] = gbase[k];
    }
    // prefetch tile 1 (warps 1..15 only; same mapping used for store)
    unsigned long long pf[5];
    int ptid = tid - 32;      // 0..479 for warps 1..15
    if (wrp > 0){
        #pragma unroll
        for (int q = 0; q < 5; q++){
            int k = ptid + q*480;
            if (k < 64*MW) pf[q] = gbase[64*MW + k];
        }
    }
    __syncthreads();

    int kept_total = 0;       // maintained by warp0 lane0 only
    for (int blk = 0; blk < MW; blk++){
        int cur   = blk % 3;
        int stbuf = (blk+1) % 3;
        int prev  = (blk+2) % 3;
        int base = blk*64;
        int nrows = PRE - base; if (nrows > 64) nrows = 64;

        if (wrp == 0){
            // serial chain (lane 0): pipelined loads + zero-chunk skip
            if (lane == 0){
                unsigned long long w0 = remv[blk];
                const unsigned long long* tp = &tile[cur][blk];
                unsigned long long bufA[8], bufB[8];
                #pragma unroll
                for (int k = 0; k < 8; k++) bufA[k] = tp[k*TS];
                #pragma unroll
                for (int c = 0; c < 8; c++){
                    if (c < 7){
                        #pragma unroll
                        for (int k = 0; k < 8; k++){
                            if (c & 1) bufA[k] = tp[((c+1)*8 + k)*TS];
                            else       bufB[k] = tp[((c+1)*8 + k)*TS];
                        }
                    }
                    unsigned long long m0 = (c & 1) ? bufB[0] : bufA[0];
                    unsigned long long m1 = (c & 1) ? bufB[1] : bufA[1];
                    unsigned long long m2 = (c & 1) ? bufB[2] : bufA[2];
                    unsigned long long m3 = (c & 1) ? bufB[3] : bufA[3];
                    unsigned long long m4 = (c & 1) ? bufB[4] : bufA[4];
                    unsigned long long m5 = (c & 1) ? bufB[5] : bufA[5];
                    unsigned long long m6 = (c & 1) ? bufB[6] : bufA[6];
                    unsigned long long m7 = (c & 1) ? bufB[7] : bufA[7];
                    unsigned long long any = m0|m1|m2|m3|m4|m5|m6|m7;
                    if (any){      // skip 8 dependent updates when chunk empty
                        unsigned long long mm[8] = {m0,m1,m2,m3,m4,m5,m6,m7};
                        #pragma unroll
                        for (int k = 0; k < 8; k++){
                            int rr = c*8 + k;
                            unsigned long long msk = ((w0 >> rr) & 1ull) - 1ull; // ~0 if alive
                            w0 |= mm[k] & msk;     // rows >= PRE have zero masks
                        }
                    }
                }
                remv[blk] = w0;
                unsigned long long validm = (nrows == 64) ? ~0ull : ((1ull << nrows) - 1ull);
                unsigned long long alive = (~w0) & validm;   // bit rr final at step rr
                sh_alive[blk & 1] = alive;
                kept_total += __popcll(alive);
                if (kept_total >= POST && blk + 1 < MW) sh_stop = blk + 1;
            }
            __syncwarp();
            // quick OR: block blk's alive rows onto word blk+1 (REDUX reduce)
            if (blk + 1 < MW){
                unsigned long long alive = sh_alive[blk & 1];
                unsigned long long acc = 0ull;
                if ((alive >> lane) & 1ull)        acc  = tile[cur][lane*TS + (blk+1)];
                if ((alive >> (lane+32)) & 1ull)   acc |= tile[cur][(lane+32)*TS + (blk+1)];
                unsigned lo = __reduce_or_sync(0xFFFFFFFFu, (unsigned)acc);
                unsigned hi = __reduce_or_sync(0xFFFFFFFFu, (unsigned)(acc >> 32));
                if (lane == 0){
                    unsigned long long a = ((unsigned long long)hi << 32) | (unsigned long long)lo;
                    if (a) atomicOr(&remv[blk+1], a);
                }
            }
        } else {
            // store prefetched tile blk+1
            if (blk + 1 < MW){
                #pragma unroll
                for (int q = 0; q < 5; q++){
                    int k = ptid + q*480;
                    if (k < 64*MW) tile[stbuf][(k >> 5)*TS + (k & 31)] = pf[q];
                }
            }
            // issue prefetch for tile blk+2
            if (blk + 2 < MW){
                const unsigned long long* gp = gbase + (size_t)(blk+2)*64*MW;
                #pragma unroll
                for (int q = 0; q < 5; q++){
                    int k = ptid + q*480;
                    if (k < 64*MW) pf[q] = gp[k];
                }
            }
            // bulk OR: block blk-1's alive rows onto words >= blk+1
            if (blk >= 1 && lane >= blk+1){
                unsigned long long alive = sh_alive[(blk-1) & 1];
                unsigned long long acc = 0ull;
                for (int rr = wrp - 1; rr < 64; rr += 15){
                    if ((alive >> rr) & 1ull) acc |= tile[prev][rr*TS + lane];
                }
                if (acc) atomicOr(&remv[lane], acc);
            }
        }
        __syncthreads();
        if (blk + 1 >= sh_stop) break;     // kept >= POST: rest irrelevant
    }

    if (tid == 0){
        int c = 0;
        for (int ww = 0; ww < MW; ww++){
            kb[ww] = c;
            unsigned long long valid = (ww == MW-1) ? 0xFFFFull : ~0ull;
            c += __popcll((~remv[ww]) & valid);
        }
        kb[MW] = c;
        g_cnt[n] = 0;           // tail: reset candidate counter for next call
    }
    __syncthreads();
    // stable partition: kept (in order) then suppressed (in order) == post top_k
    for (int i = tid; i < PRE; i += 512){
        int ww = i >> 6, b = i & 63;
        unsigned long long valid = (ww == MW-1) ? 0xFFFFull : ~0ull;
        unsigned long long notr = (~remv[ww]) & valid;
        bool keep = (notr >> b) & 1ull;
        unsigned long long below = b ? (notr & ((~0ull) >> (64 - b))) : 0ull;
        int kbelow = kb[ww] + __popcll(below);
        int pos = keep ? kbelow : (kb[MW] + (i - kbelow));
        if (pos < POST){
            float4 bx = g_boxes[n*PRE + i];
            float sc = keep ? g_sc[n*PRE + i] : -1.0f;
            float* op = out + ((size_t)n*POST + pos)*5;
            op[0]=bx.x; op[1]=bx.y; op[2]=bx.z; op[3]=bx.w; op[4]=sc;
        }
    }
}

extern "C" void kernel_launch(void* const* d_in, const int* in_sizes, int n_in,
                              void* d_out, int out_size){
    (void)in_sizes; (void)n_in; (void)out_size;
    const float* logits  = (const float*)d_in[0];
    const float* regs    = (const float*)d_in[1];
    const float* anchors = (const float*)d_in[2];
    const int*   sizes   = (const int*)d_in[3];
    float* out = (float*)d_out;

    dim3 g((AHW4 + 255)/256, NB);
    k_hist<<<g, 256>>>((const float4*)logits);
    k_sortdecode<<<NB, 1024>>>((const float4*)logits, regs, anchors, sizes);
    k_mask<<<dim3(528, NB), 256>>>();
    k_scan<<<NB, 512>>>(out);
}